// round 16
// baseline (speedup 1.0000x reference)
#include <cuda_runtime.h>
#include <cuda_bf16.h>
#include <math_constants.h>
#include <cstdint>

#define BB 4
#define TT 4096
#define DD 1024
#define HH 64
#define NROW (BB*TT)
#define NSPLIT 4

// scale/sqrt(H) folded with log2(e): 0.125 * 1.4426950408889634
#define SCALE_L2E 0.18033688011112790f

// Scratch — __device__ globals per allocation rules.
__device__ unsigned short g_Wthi[3*HH*DD];    // W^T split-bf16: [m][n][k]
__device__ unsigned short g_Wtlo[3*HH*DD];
__device__ unsigned short g_Khi[NROW*HH];     // k,q split-bf16 (row-major)
__device__ unsigned short g_Klo[NROW*HH];
__device__ unsigned short g_Qhi[NROW*HH];
__device__ unsigned short g_Qlo[NROW*HH];
__device__ unsigned short g_Vthi[BB*HH*TT];   // v split-bf16 TRANSPOSED: [b][h][t]
__device__ unsigned short g_Vtlo[BB*HH*TT];
__device__ float g_Oa[NSPLIT*NROW*HH];        // split partial O (unnormalized)
__device__ float g_M[NSPLIT*NROW];            // running max (log2 domain)
__device__ float g_L[NSPLIT*NROW];

// ---------------- helpers ----------------
__device__ __forceinline__ uint32_t swz(uint32_t o) { return o ^ ((o >> 3) & 0x70); }

__device__ __forceinline__ uint32_t smem_u32(const void* p) {
    uint32_t a;
    asm("{ .reg .u64 t; cvta.to.shared.u64 t, %1; cvt.u32.u64 %0, t; }"
        : "=r"(a) : "l"(p));
    return a;
}
__device__ __forceinline__ float ex2f(float x) {
    float r; asm("ex2.approx.f32 %0, %1;" : "=f"(r) : "f"(x)); return r;
}

// FAST split: hi = truncate-to-bf16 (top 16 bits), lo = exact residual, RN.
__device__ __forceinline__ void bf_split2(float x0, float x1, uint32_t& hi, uint32_t& lo) {
    uint32_t u0 = __float_as_uint(x0), u1 = __float_as_uint(x1);
    hi = __byte_perm(u0, u1, 0x7632);            // {hi16(x1), hi16(x0)}
    float h0 = __uint_as_float(u0 & 0xFFFF0000u);
    float h1 = __uint_as_float(u1 & 0xFFFF0000u);
    float l0 = x0 - h0, l1 = x1 - h1;            // exact
    asm("cvt.rn.bf16x2.f32 %0, %1, %2;" : "=r"(lo) : "f"(l1), "f"(l0));
}

__device__ __forceinline__ void mma16816(float (&d)[4], const uint32_t (&a)[4],
                                         const uint32_t (&b)[2]) {
    asm volatile(
        "mma.sync.aligned.m16n8k16.row.col.f32.bf16.bf16.f32 "
        "{%0,%1,%2,%3}, {%4,%5,%6,%7}, {%8,%9}, {%0,%1,%2,%3};"
        : "+f"(d[0]), "+f"(d[1]), "+f"(d[2]), "+f"(d[3])
        : "r"(a[0]), "r"(a[1]), "r"(a[2]), "r"(a[3]), "r"(b[0]), "r"(b[1]));
}
__device__ __forceinline__ void mma3(float (&d)[4], const uint32_t (&ah)[4],
                                     const uint32_t (&al)[4], const uint32_t (&bh)[2],
                                     const uint32_t (&bl)[2]) {
    mma16816(d, ah, bh);
    mma16816(d, ah, bl);
    mma16816(d, al, bh);
}

__device__ __forceinline__ void ldsm4(uint32_t (&r)[4], uint32_t saddr) {
    asm volatile("ldmatrix.sync.aligned.m8n8.x4.shared.b16 {%0,%1,%2,%3}, [%4];"
        : "=r"(r[0]), "=r"(r[1]), "=r"(r[2]), "=r"(r[3]) : "r"(saddr));
}
// B fragments for n-tiles j and j+1, k-step kk, from row-major [n][k] SW128 tile.
__device__ __forceinline__ void ldB4(uint32_t (&r)[4], uint32_t base, int j, int kk) {
    int lane = threadIdx.x & 31;
    int rsel = lane & 7, sel = lane >> 3;
    uint32_t byte = (uint32_t)((8 * (j + (sel >> 1)) + rsel) * 128 + kk * 32 + (sel & 1) * 16);
    ldsm4(r, base + swz(byte));
}
// A fragments (rows R..R+15, k-step kk) from row-major SW128 tile.
__device__ __forceinline__ void ldA4(uint32_t (&r)[4], uint32_t base, int R, int kk) {
    int lane = threadIdx.x & 31;
    int rsel = lane & 7, sel = lane >> 3;
    uint32_t byte = (uint32_t)((R + (sel & 1) * 8 + rsel) * 128 + kk * 32 + (sel >> 1) * 16);
    ldsm4(r, base + swz(byte));
}

// ---- cp.async (LDGSTS) helpers ----
__device__ __forceinline__ void cp16(uint32_t dst, const void* src) {
    asm volatile("cp.async.cg.shared.global [%0], [%1], 16;" :: "r"(dst), "l"(src));
}
#define CP_COMMIT() asm volatile("cp.async.commit_group;" ::: "memory")
#define CP_WAIT(n)  asm volatile("cp.async.wait_group %0;" :: "n"(n) : "memory")

// async-load a 64x64 bf16 tile (row stride lds ushorts) into SW128 smem. 128 thr.
__device__ __forceinline__ void cp_tile64_t128(const unsigned short* __restrict__ g,
                                               int lds, uint32_t sbase, int tid) {
    int r = tid >> 1, half = (tid & 1) * 64;
    const char* gp = (const char*)(g + (size_t)r * lds) + half;
    uint32_t o = (uint32_t)(r * 128 + half);
#pragma unroll
    for (int i = 0; i < 4; i++)
        cp16(sbase + swz(o + 16 * i), gp + 16 * i);
}

// ---------------------------------------------------------------------------
// cvt_w: W[k][n] fp32 -> Wt[m][n][k] bf16 hi/lo. grid 24 x 128.
// ---------------------------------------------------------------------------
__global__ __launch_bounds__(128)
void cvt_w_kernel(const float* __restrict__ Wk, const float* __restrict__ Wq,
                  const float* __restrict__ Wv)
{
    const int m = blockIdx.x >> 3;
    const int n = (blockIdx.x & 7) * 8 + (threadIdx.x >> 4);
    const int k0 = (threadIdx.x & 15) * 64;
    const float* W = (m == 0) ? Wk : (m == 1) ? Wq : Wv;
    const size_t base = (size_t)m * HH * DD + (size_t)n * DD;
#pragma unroll 4
    for (int kk = 0; kk < 32; kk++) {
        int k = k0 + 2 * kk;
        float f0 = W[(size_t)k * HH + n];
        float f1 = W[(size_t)(k + 1) * HH + n];
        uint32_t hi, lo;
        bf_split2(f0, f1, hi, lo);
        *(uint32_t*)(g_Wthi + base + k) = hi;
        *(uint32_t*)(g_Wtlo + base + k) = lo;
    }
}

// ---------------------------------------------------------------------------
// Merged QKV, pipelined (unchanged from R14): 64 rows x 192 cols per CTA.
// ---------------------------------------------------------------------------
#define QKV_SMEM (114688 + 1024)
__global__ __launch_bounds__(256, 2)
void qkv_kernel(const float* __restrict__ x,
                const float* __restrict__ bk, const float* __restrict__ bq,
                const float* __restrict__ bv)
{
    extern __shared__ char dsm[];
    char* smc = (char*)(((uintptr_t)dsm + 1023) & ~(uintptr_t)1023);
    char* Xhi = smc;          char* Xlo = smc + 8192;
    const uint32_t xhi_b = smem_u32(Xhi), xlo_b = smem_u32(Xlo);
    const uint32_t wbase = smem_u32(smc + 16384);

    const int tid = threadIdx.x;
    const int wid = tid >> 5, lane = tid & 31;
    const int g = lane >> 2, t = lane & 3;
    const int rw = wid & 3, cg = wid >> 2;
    const int R = 16 * rw;
    const int row0 = blockIdx.x * 64;

    const int xr_r = tid >> 2, xr_q = tid & 3;
    const float* xrow = x + (size_t)(row0 + xr_r) * DD + xr_q * 16;

    float dD[12][4] = {};
    float4 xr[4];

#pragma unroll
    for (int i = 0; i < 4; i++) xr[i] = *(const float4*)(xrow + 4 * i);
    {
        for (int task = tid; task < 768; task += 256) {
            int isLo = task >= 384;
            int tk = isLo ? task - 384 : task;
            int rr = tk >> 1, hf = tk & 1;
            const unsigned short* gw = isLo ? g_Wtlo : g_Wthi;
            uint32_t sb = wbase + (isLo ? 24576u : 0u);
            const char* gp = (const char*)(gw + (size_t)rr * DD + hf * 32);
#pragma unroll
            for (int i = 0; i < 4; i++)
                cp16(sb + swz((uint32_t)(rr * 128 + hf * 64 + 16 * i)), gp + 16 * i);
        }
        CP_COMMIT();
    }

#pragma unroll 1
    for (int kc = 0; kc < 16; kc++) {
        __syncthreads();
        {
            uint4 hi, lo;
            bf_split2(xr[0].x, xr[0].y, hi.x, lo.x);
            bf_split2(xr[0].z, xr[0].w, hi.y, lo.y);
            bf_split2(xr[1].x, xr[1].y, hi.z, lo.z);
            bf_split2(xr[1].z, xr[1].w, hi.w, lo.w);
            uint32_t off = swz((uint32_t)(xr_r * 128 + xr_q * 32));
            *(uint4*)(Xhi + off) = hi;
            *(uint4*)(Xlo + off) = lo;
            bf_split2(xr[2].x, xr[2].y, hi.x, lo.x);
            bf_split2(xr[2].z, xr[2].w, hi.y, lo.y);
            bf_split2(xr[3].x, xr[3].y, hi.z, lo.z);
            bf_split2(xr[3].z, xr[3].w, hi.w, lo.w);
            off = swz((uint32_t)(xr_r * 128 + xr_q * 32 + 16));
            *(uint4*)(Xhi + off) = hi;
            *(uint4*)(Xlo + off) = lo;
        }
        if (kc < 15) {
            uint32_t wb = wbase + (uint32_t)((kc + 1) & 1) * 49152u;
            for (int task = tid; task < 768; task += 256) {
                int isLo = task >= 384;
                int tk = isLo ? task - 384 : task;
                int rr = tk >> 1, hf = tk & 1;
                const unsigned short* gw = isLo ? g_Wtlo : g_Wthi;
                uint32_t sb = wb + (isLo ? 24576u : 0u);
                const char* gp = (const char*)(gw + (size_t)rr * DD + (kc + 1) * 64 + hf * 32);
#pragma unroll
                for (int i = 0; i < 4; i++)
                    cp16(sb + swz((uint32_t)(rr * 128 + hf * 64 + 16 * i)), gp + 16 * i);
            }
            CP_COMMIT();
#pragma unroll
            for (int i = 0; i < 4; i++)
                xr[i] = *(const float4*)(xrow + (kc + 1) * 64 + 4 * i);
            CP_WAIT(1);
        } else {
            CP_WAIT(0);
        }
        __syncthreads();

        const uint32_t whi_b = wbase + (uint32_t)(kc & 1) * 49152u;
        const uint32_t wlo_b = whi_b + 24576u;
#pragma unroll
        for (int kk = 0; kk < 4; kk++) {
            uint32_t ah[4], al[4];
            ldA4(ah, xhi_b, R, kk);
            ldA4(al, xlo_b, R, kk);
#pragma unroll
            for (int jl = 0; jl < 6; jl++) {
                uint32_t wh[4], wl[4];
                ldB4(wh, whi_b, cg * 12 + 2 * jl, kk);
                ldB4(wl, wlo_b, cg * 12 + 2 * jl, kk);
                uint32_t bh0[2] = { wh[0], wh[1] }, bl0[2] = { wl[0], wl[1] };
                uint32_t bh1[2] = { wh[2], wh[3] }, bl1[2] = { wl[2], wl[3] };
                mma3(dD[2 * jl],     ah, al, bh0, bl0);
                mma3(dD[2 * jl + 1], ah, al, bh1, bl1);
            }
        }
    }

    const int r1 = R + g, r2 = r1 + 8;
    float* Vst = (float*)smc;
    __syncthreads();
#pragma unroll
    for (int jl = 0; jl < 12; jl++) {
        int jt = cg * 12 + jl;
        int cgl = 8 * jt + 2 * t;
        int mi = cgl >> 6, cm = cgl & 63;
        if (mi < 2) {
            const float* bias = mi ? bq : bk;
            unsigned short* ohi = mi ? g_Qhi : g_Khi;
            unsigned short* olo = mi ? g_Qlo : g_Klo;
            float b0 = bias[cm], b1 = bias[cm + 1];
            uint32_t hi, lo;
            bf_split2(dD[jl][0] + b0, dD[jl][1] + b1, hi, lo);
            *(uint32_t*)(ohi + (size_t)(row0 + r1) * HH + cm) = hi;
            *(uint32_t*)(olo + (size_t)(row0 + r1) * HH + cm) = lo;
            bf_split2(dD[jl][2] + b0, dD[jl][3] + b1, hi, lo);
            *(uint32_t*)(ohi + (size_t)(row0 + r2) * HH + cm) = hi;
            *(uint32_t*)(olo + (size_t)(row0 + r2) * HH + cm) = lo;
        } else {
            float b0 = bv[cm], b1 = bv[cm + 1];
            Vst[r1 * 64 + cm] = dD[jl][0] + b0;
            Vst[r1 * 64 + cm + 1] = dD[jl][1] + b1;
            Vst[r2 * 64 + cm] = dD[jl][2] + b0;
            Vst[r2 * 64 + cm + 1] = dD[jl][3] + b1;
        }
    }
    __syncthreads();
    {
        const int b    = row0 >> 12;
        const int tloc = row0 & (TT - 1);
        const int h  = tid & 63;
        const int s0 = (tid >> 6) * 16;
        const size_t obase = (size_t)b * HH * TT + (size_t)h * TT + tloc + s0;
#pragma unroll
        for (int jj = 0; jj < 16; jj += 8) {
            uint4 hi, lo;
            bf_split2(Vst[(s0 + jj + 0) * 64 + h], Vst[(s0 + jj + 1) * 64 + h], hi.x, lo.x);
            bf_split2(Vst[(s0 + jj + 2) * 64 + h], Vst[(s0 + jj + 3) * 64 + h], hi.y, lo.y);
            bf_split2(Vst[(s0 + jj + 4) * 64 + h], Vst[(s0 + jj + 5) * 64 + h], hi.z, lo.z);
            bf_split2(Vst[(s0 + jj + 6) * 64 + h], Vst[(s0 + jj + 7) * 64 + h], hi.w, lo.w);
            *(uint4*)(g_Vthi + obase + jj) = hi;
            *(uint4*)(g_Vtlo + obase + jj) = lo;
        }
    }
}

// ---------------------------------------------------------------------------
// HMMA flash attention, m32-per-warp: 4 warps (128 thr) x 32 rows = 128 t-rows.
// Each B (Q/V) fragment load is amortized over 2 MMA tiles -> per-CTA LDSM
// traffic nearly halves vs 8xm16. cp.async double-buffered Q/V tiles.
// 4-way split-K -> 512 CTAs descending by work. Log2-domain softmax.
// ---------------------------------------------------------------------------
#define ATT_SMEM (98304 + 1024)
__global__ __launch_bounds__(128, 2)
void attn_mma_kernel()
{
    extern __shared__ char dsm[];
    char* smc = (char*)(((uintptr_t)dsm + 1023) & ~(uintptr_t)1023);
    const uint32_t sa_b = smem_u32(smc);
    // layout: K hi [0,16K), K lo [16K,32K); buffers at 32K and 64K:
    //   each buffer: Qhi +0, Qlo +8K, Vhi +16K, Vlo +24K

    const int tid = threadIdx.x;
    const int wid = tid >> 5, lane = tid & 31;
    const int g = lane >> 2, t = lane & 3;
    const int R = 32 * wid;                     // this warp's 32 rows

    const int bid   = blockIdx.x;               // 0..511
    const int bt    = 31 - (bid >> 4);          // descending work order
    const int sub   = bid & 15;
    const int b     = sub >> 2;
    const int split = sub & 3;
    const int n     = 2 * bt + 2;
    const int st_lo = (split * n) >> 2;
    const int st_hi = (((split + 1) * n) >> 2) - 1;

    const size_t Rg = (size_t)b * TT + (size_t)bt * 128;
    const size_t vb = (size_t)b * HH * TT;
    const size_t qb = (size_t)b * TT;
    // global rows of the 4 accumulator row-groups: R+g, +8, +16, +24
    int trow[4];
#pragma unroll
    for (int i = 0; i < 4; i++) trow[i] = bt * 128 + R + g + 8 * i;

    // ---- stage K (128 rows hi/lo): 1 row per thread ----
    {
        int r = tid;
        const char* gph = (const char*)(g_Khi + (Rg + r) * HH);
        const char* gpl = (const char*)(g_Klo + (Rg + r) * HH);
#pragma unroll
        for (int i = 0; i < 8; i++) {
            uint4 vh = *(const uint4*)(gph + 16 * i);
            uint4 vl = *(const uint4*)(gpl + 16 * i);
            uint32_t off = swz((uint32_t)(r * 128 + 16 * i));
            *(uint4*)(smc + off) = vh;
            *(uint4*)(smc + 16384 + off) = vl;
        }
    }

    float dO[2][8][4] = {};
    float m[4], l[4];
#pragma unroll
    for (int i = 0; i < 4; i++) { m[i] = -CUDART_INF_F; l[i] = 0.f; }

    if (st_lo <= st_hi) {
        // prologue prefetch
        {
            uint32_t bb = sa_b + 32768;
            cp_tile64_t128(g_Qhi + (qb + (size_t)st_lo * 64) * HH, HH, bb, tid);
            cp_tile64_t128(g_Qlo + (qb + (size_t)st_lo * 64) * HH, HH, bb + 8192, tid);
            cp_tile64_t128(g_Vthi + vb + st_lo * 64, TT, bb + 16384, tid);
            cp_tile64_t128(g_Vtlo + vb + st_lo * 64, TT, bb + 24576, tid);
            CP_COMMIT();
        }
#pragma unroll 1
        for (int st = st_lo; st <= st_hi; st++) {
            const int cur = (st - st_lo) & 1;
            const uint32_t cb = sa_b + 32768 + (uint32_t)cur * 32768;
            if (st < st_hi) {
                uint32_t nb = sa_b + 32768 + (uint32_t)(cur ^ 1) * 32768;
                cp_tile64_t128(g_Qhi + (qb + (size_t)(st + 1) * 64) * HH, HH, nb, tid);
                cp_tile64_t128(g_Qlo + (qb + (size_t)(st + 1) * 64) * HH, HH, nb + 8192, tid);
                cp_tile64_t128(g_Vthi + vb + (st + 1) * 64, TT, nb + 16384, tid);
                cp_tile64_t128(g_Vtlo + vb + (st + 1) * 64, TT, nb + 24576, tid);
                CP_COMMIT();
                CP_WAIT(1);
            } else {
                CP_WAIT(0);
            }
            __syncthreads();
            const uint32_t qhi_b = cb, qlo_b = cb + 8192;
            const uint32_t vhi_b = cb + 16384, vlo_b = cb + 24576;

            // ---- S = K @ Q^T : 2 m16 tiles share each Q fragment ----
            float dS[2][8][4] = {};
#pragma unroll
            for (int kk = 0; kk < 4; kk++) {
                uint32_t kfh[2][4], kfl[2][4];
#pragma unroll
                for (int mt = 0; mt < 2; mt++) {
                    ldA4(kfh[mt], sa_b, R + 16 * mt, kk);
                    ldA4(kfl[mt], sa_b + 16384, R + 16 * mt, kk);
                }
#pragma unroll
                for (int jp = 0; jp < 4; jp++) {
                    uint32_t qh[4], ql[4];
                    ldB4(qh, qhi_b, 2 * jp, kk);
                    ldB4(ql, qlo_b, 2 * jp, kk);
                    uint32_t bh0[2] = { qh[0], qh[1] }, bl0[2] = { ql[0], ql[1] };
                    uint32_t bh1[2] = { qh[2], qh[3] }, bl1[2] = { ql[2], ql[3] };
#pragma unroll
                    for (int mt = 0; mt < 2; mt++) {
                        mma3(dS[mt][2 * jp],     kfh[mt], kfl[mt], bh0, bl0);
                        mma3(dS[mt][2 * jp + 1], kfh[mt], kfl[mt], bh1, bl1);
                    }
                }
            }

            // ---- scale (log2 domain) + causal mask ----
            if (st >= 2 * bt) {
#pragma unroll
                for (int mt = 0; mt < 2; mt++)
#pragma unroll
                    for (int j = 0; j < 8; j++) {
                        int c0 = st * 64 + 8 * j + 2 * t;
                        int rA = trow[2 * mt], rB = trow[2 * mt + 1];
                        dS[mt][j][0] = (c0     <= rA) ? dS[mt][j][0] * SCALE_L2E : -1e30f;
                        dS[mt][j][1] = (c0 + 1 <= rA) ? dS[mt][j][1] * SCALE_L2E : -1e30f;
                        dS[mt][j][2] = (c0     <= rB) ? dS[mt][j][2] * SCALE_L2E : -1e30f;
                        dS[mt][j][3] = (c0 + 1 <= rB) ? dS[mt][j][3] * SCALE_L2E : -1e30f;
                    }
            } else {
#pragma unroll
                for (int mt = 0; mt < 2; mt++)
#pragma unroll
                    for (int j = 0; j < 8; j++) {
                        dS[mt][j][0] *= SCALE_L2E; dS[mt][j][1] *= SCALE_L2E;
                        dS[mt][j][2] *= SCALE_L2E; dS[mt][j][3] *= SCALE_L2E;
                    }
            }

            // ---- online softmax (base-2), 4 row-groups ----
            float rmax[4] = { -CUDART_INF_F, -CUDART_INF_F, -CUDART_INF_F, -CUDART_INF_F };
#pragma unroll
            for (int mt = 0; mt < 2; mt++)
#pragma unroll
                for (int j = 0; j < 8; j++) {
                    rmax[2 * mt]     = fmaxf(rmax[2 * mt],     fmaxf(dS[mt][j][0], dS[mt][j][1]));
                    rmax[2 * mt + 1] = fmaxf(rmax[2 * mt + 1], fmaxf(dS[mt][j][2], dS[mt][j][3]));
                }
            float corr[4], sum[4] = {};
#pragma unroll
            for (int i = 0; i < 4; i++) {
                rmax[i] = fmaxf(rmax[i], __shfl_xor_sync(0xffffffffu, rmax[i], 1));
                rmax[i] = fmaxf(rmax[i], __shfl_xor_sync(0xffffffffu, rmax[i], 2));
                float mn = fmaxf(m[i], rmax[i]);
                corr[i] = ex2f(m[i] - mn);
                m[i] = mn;
            }
#pragma unroll
            for (int mt = 0; mt < 2; mt++)
#pragma unroll
                for (int j = 0; j < 8; j++) {
                    dS[mt][j][0] = ex2f(dS[mt][j][0] - m[2 * mt]);
                    dS[mt][j][1] = ex2f(dS[mt][j][1] - m[2 * mt]);
                    dS[mt][j][2] = ex2f(dS[mt][j][2] - m[2 * mt + 1]);
                    dS[mt][j][3] = ex2f(dS[mt][j][3] - m[2 * mt + 1]);
                    sum[2 * mt]     += dS[mt][j][0] + dS[mt][j][1];
                    sum[2 * mt + 1] += dS[mt][j][2] + dS[mt][j][3];
                }
#pragma unroll
            for (int i = 0; i < 4; i++) {
                sum[i] += __shfl_xor_sync(0xffffffffu, sum[i], 1);
                sum[i] += __shfl_xor_sync(0xffffffffu, sum[i], 2);
                l[i] = l[i] * corr[i] + sum[i];
            }
#pragma unroll
            for (int mt = 0; mt < 2; mt++)
#pragma unroll
                for (int j = 0; j < 8; j++) {
                    dO[mt][j][0] *= corr[2 * mt];     dO[mt][j][1] *= corr[2 * mt];
                    dO[mt][j][2] *= corr[2 * mt + 1]; dO[mt][j][3] *= corr[2 * mt + 1];
                }

            // ---- O += P @ V : 2 m16 tiles share each V fragment ----
#pragma unroll
            for (int ss = 0; ss < 4; ss++) {
                uint32_t pah[2][4], pal[2][4];
#pragma unroll
                for (int mt = 0; mt < 2; mt++) {
                    bf_split2(dS[mt][2*ss][0],   dS[mt][2*ss][1],   pah[mt][0], pal[mt][0]);
                    bf_split2(dS[mt][2*ss][2],   dS[mt][2*ss][3],   pah[mt][1], pal[mt][1]);
                    bf_split2(dS[mt][2*ss+1][0], dS[mt][2*ss+1][1], pah[mt][2], pal[mt][2]);
                    bf_split2(dS[mt][2*ss+1][2], dS[mt][2*ss+1][3], pah[mt][3], pal[mt][3]);
                }
#pragma unroll
                for (int jp = 0; jp < 4; jp++) {
                    uint32_t vh[4], vl[4];
                    ldB4(vh, vhi_b, 2 * jp, ss);
                    ldB4(vl, vlo_b, 2 * jp, ss);
                    uint32_t bh0[2] = { vh[0], vh[1] }, bl0[2] = { vl[0], vl[1] };
                    uint32_t bh1[2] = { vh[2], vh[3] }, bl1[2] = { vl[2], vl[3] };
#pragma unroll
                    for (int mt = 0; mt < 2; mt++) {
                        mma3(dO[mt][2 * jp],     pah[mt], pal[mt], bh0, bl0);
                        mma3(dO[mt][2 * jp + 1], pah[mt], pal[mt], bh1, bl1);
                    }
                }
            }
            __syncthreads();   // reads of cb done before it is refilled
        }
    }

    // ---- write unnormalized partial + (m, l) ----
#pragma unroll
    for (int mt = 0; mt < 2; mt++) {
        const size_t orow1 = (size_t)split * NROW + Rg + R + 16 * mt + g;
        const size_t orow2 = orow1 + 8;
#pragma unroll
        for (int j = 0; j < 8; j++) {
            int c = 8 * j + 2 * t;
            *(float2*)(g_Oa + orow1 * HH + c) = make_float2(dO[mt][j][0], dO[mt][j][1]);
            *(float2*)(g_Oa + orow2 * HH + c) = make_float2(dO[mt][j][2], dO[mt][j][3]);
        }
        if (t == 0) {
            g_M[orow1] = m[2 * mt];     g_L[orow1] = l[2 * mt];
            g_M[orow2] = m[2 * mt + 1]; g_L[orow2] = l[2 * mt + 1];
        }
    }
}

// ---------------------------------------------------------------------------
// Merge the four split partials (m stored in log2 domain -> ex2).
// ---------------------------------------------------------------------------
__global__ __launch_bounds__(256)
void combine_kernel(float* __restrict__ out)
{
    int gid = blockIdx.x * 256 + threadIdx.x;
    int r = gid >> 4, lane = gid & 15;
    float m[NSPLIT], l[NSPLIT];
#pragma unroll
    for (int i = 0; i < NSPLIT; i++) {
        m[i] = g_M[(size_t)i * NROW + r];
        l[i] = g_L[(size_t)i * NROW + r];
    }
    float M = fmaxf(fmaxf(m[0], m[1]), fmaxf(m[2], m[3]));
    float denom = 0.f, e[NSPLIT];
#pragma unroll
    for (int i = 0; i < NSPLIT; i++) {
        e[i] = ex2f(m[i] - M);
        denom += l[i] * e[i];
    }
    float inv = 1.0f / denom;
    float4 acc = make_float4(0.f, 0.f, 0.f, 0.f);
#pragma unroll
    for (int i = 0; i < NSPLIT; i++) {
        float4 a = *(const float4*)(g_Oa + ((size_t)i * NROW + r) * HH + 4 * lane);
        acc.x += a.x * e[i]; acc.y += a.y * e[i];
        acc.z += a.z * e[i]; acc.w += a.w * e[i];
    }
    acc.x *= inv; acc.y *= inv; acc.z *= inv; acc.w *= inv;
    *(float4*)(out + (size_t)r * HH + 4 * lane) = acc;
}

extern "C" void kernel_launch(void* const* d_in, const int* in_sizes, int n_in,
                              void* d_out, int out_size)
{
    const float* x  = (const float*)d_in[0];
    const float* Wk = (const float*)d_in[1];
    const float* bk = (const float*)d_in[2];
    const float* Wq = (const float*)d_in[3];
    const float* bq = (const float*)d_in[4];
    const float* Wv = (const float*)d_in[5];
    const float* bv = (const float*)d_in[6];
    float* out = (float*)d_out;

    static bool attr_done = false;
    if (!attr_done) {
        cudaFuncSetAttribute(qkv_kernel,
            cudaFuncAttributeMaxDynamicSharedMemorySize, QKV_SMEM);
        cudaFuncSetAttribute(attn_mma_kernel,
            cudaFuncAttributeMaxDynamicSharedMemorySize, ATT_SMEM);
        attr_done = true;
    }

    cvt_w_kernel<<<24, 128>>>(Wk, Wq, Wv);

    qkv_kernel<<<NROW / 64, 256, QKV_SMEM>>>(x, bk, bq, bv);

    attn_mma_kernel<<<512, 128, ATT_SMEM>>>();

    combine_kernel<<<NROW * 16 / 256, 256>>>(out);
}

// round 17
// speedup vs baseline: 1.0388x; 1.0388x over previous
#include <cuda_runtime.h>
#include <cuda_bf16.h>
#include <math_constants.h>
#include <cstdint>

#define BB 4
#define TT 4096
#define DD 1024
#define HH 64
#define NROW (BB*TT)
#define NSPLIT 4

// scale/sqrt(H) folded with log2(e): 0.125 * 1.4426950408889634
#define SCALE_L2E 0.18033688011112790f

// Scratch — __device__ globals per allocation rules.
__device__ unsigned short g_Wthi[3*HH*DD];    // W^T split-bf16: [m][n][k]
__device__ unsigned short g_Wtlo[3*HH*DD];
__device__ unsigned short g_Khi[NROW*HH];     // k,q split-bf16 (row-major)
__device__ unsigned short g_Klo[NROW*HH];
__device__ unsigned short g_Qhi[NROW*HH];
__device__ unsigned short g_Qlo[NROW*HH];
__device__ unsigned short g_Vthi[BB*HH*TT];   // v split-bf16 TRANSPOSED: [b][h][t]
__device__ unsigned short g_Vtlo[BB*HH*TT];
__device__ float g_Oa[NSPLIT*NROW*HH];        // split partial O (unnormalized)
__device__ float g_M[NSPLIT*NROW];            // running max (log2 domain)
__device__ float g_L[NSPLIT*NROW];

// ---------------- helpers ----------------
__device__ __forceinline__ uint32_t swz(uint32_t o) { return o ^ ((o >> 3) & 0x70); }

__device__ __forceinline__ uint32_t smem_u32(const void* p) {
    uint32_t a;
    asm("{ .reg .u64 t; cvta.to.shared.u64 t, %1; cvt.u32.u64 %0, t; }"
        : "=r"(a) : "l"(p));
    return a;
}
__device__ __forceinline__ float ex2f(float x) {
    float r; asm("ex2.approx.f32 %0, %1;" : "=f"(r) : "f"(x)); return r;
}

// FAST split: hi = truncate-to-bf16 (top 16 bits), lo = exact residual, RN.
__device__ __forceinline__ void bf_split2(float x0, float x1, uint32_t& hi, uint32_t& lo) {
    uint32_t u0 = __float_as_uint(x0), u1 = __float_as_uint(x1);
    hi = __byte_perm(u0, u1, 0x7632);            // {hi16(x1), hi16(x0)}
    float h0 = __uint_as_float(u0 & 0xFFFF0000u);
    float h1 = __uint_as_float(u1 & 0xFFFF0000u);
    float l0 = x0 - h0, l1 = x1 - h1;            // exact
    asm("cvt.rn.bf16x2.f32 %0, %1, %2;" : "=r"(lo) : "f"(l1), "f"(l0));
}

__device__ __forceinline__ void mma16816(float (&d)[4], const uint32_t (&a)[4],
                                         const uint32_t (&b)[2]) {
    asm volatile(
        "mma.sync.aligned.m16n8k16.row.col.f32.bf16.bf16.f32 "
        "{%0,%1,%2,%3}, {%4,%5,%6,%7}, {%8,%9}, {%0,%1,%2,%3};"
        : "+f"(d[0]), "+f"(d[1]), "+f"(d[2]), "+f"(d[3])
        : "r"(a[0]), "r"(a[1]), "r"(a[2]), "r"(a[3]), "r"(b[0]), "r"(b[1]));
}
__device__ __forceinline__ void mma3(float (&d)[4], const uint32_t (&ah)[4],
                                     const uint32_t (&al)[4], const uint32_t (&bh)[2],
                                     const uint32_t (&bl)[2]) {
    mma16816(d, ah, bh);
    mma16816(d, ah, bl);
    mma16816(d, al, bh);
}

__device__ __forceinline__ void ldsm4(uint32_t (&r)[4], uint32_t saddr) {
    asm volatile("ldmatrix.sync.aligned.m8n8.x4.shared.b16 {%0,%1,%2,%3}, [%4];"
        : "=r"(r[0]), "=r"(r[1]), "=r"(r[2]), "=r"(r[3]) : "r"(saddr));
}
// B fragments for n-tiles j and j+1, k-step kk, from row-major [n][k] SW128 tile.
__device__ __forceinline__ void ldB4(uint32_t (&r)[4], uint32_t base, int j, int kk) {
    int lane = threadIdx.x & 31;
    int rsel = lane & 7, sel = lane >> 3;
    uint32_t byte = (uint32_t)((8 * (j + (sel >> 1)) + rsel) * 128 + kk * 32 + (sel & 1) * 16);
    ldsm4(r, base + swz(byte));
}
// A fragments (rows R..R+15, k-step kk) from row-major SW128 tile.
__device__ __forceinline__ void ldA4(uint32_t (&r)[4], uint32_t base, int R, int kk) {
    int lane = threadIdx.x & 31;
    int rsel = lane & 7, sel = lane >> 3;
    uint32_t byte = (uint32_t)((R + (sel & 1) * 8 + rsel) * 128 + kk * 32 + (sel >> 1) * 16);
    ldsm4(r, base + swz(byte));
}

// ---- cp.async (LDGSTS) helpers ----
__device__ __forceinline__ void cp16(uint32_t dst, const void* src) {
    asm volatile("cp.async.cg.shared.global [%0], [%1], 16;" :: "r"(dst), "l"(src));
}
#define CP_COMMIT() asm volatile("cp.async.commit_group;" ::: "memory")
#define CP_WAIT(n)  asm volatile("cp.async.wait_group %0;" :: "n"(n) : "memory")

// async-load a 64x64 bf16 tile (row stride lds ushorts) into SW128 smem. 256 thr.
__device__ __forceinline__ void cp_tile64(const unsigned short* __restrict__ g,
                                          int lds, uint32_t sbase, int tid) {
    int r = tid >> 2, q = tid & 3;
    const char* gp = (const char*)(g + (size_t)r * lds + q * 16);
    uint32_t o = (uint32_t)(r * 128 + q * 32);
    cp16(sbase + swz(o), gp);
    cp16(sbase + swz(o + 16), gp + 16);
}

// ---------------------------------------------------------------------------
// cvt_w: W[k][n] fp32 -> Wt[m][n][k] bf16 hi/lo. grid 24 x 128.
// ---------------------------------------------------------------------------
__global__ __launch_bounds__(128)
void cvt_w_kernel(const float* __restrict__ Wk, const float* __restrict__ Wq,
                  const float* __restrict__ Wv)
{
    const int m = blockIdx.x >> 3;
    const int n = (blockIdx.x & 7) * 8 + (threadIdx.x >> 4);
    const int k0 = (threadIdx.x & 15) * 64;
    const float* W = (m == 0) ? Wk : (m == 1) ? Wq : Wv;
    const size_t base = (size_t)m * HH * DD + (size_t)n * DD;
#pragma unroll 4
    for (int kk = 0; kk < 32; kk++) {
        int k = k0 + 2 * kk;
        float f0 = W[(size_t)k * HH + n];
        float f1 = W[(size_t)(k + 1) * HH + n];
        uint32_t hi, lo;
        bf_split2(f0, f1, hi, lo);
        *(uint32_t*)(g_Wthi + base + k) = hi;
        *(uint32_t*)(g_Wtlo + base + k) = lo;
    }
}

// ---------------------------------------------------------------------------
// Merged QKV (R13 config): 64 rows x 192 cols per CTA (256 CTAs), 2 CTAs/SM.
// 256 threads = 4 row-warps x 2 col-groups. W via cp.async overlap.
// ---------------------------------------------------------------------------
#define QKV_SMEM (65536 + 1024)
__global__ __launch_bounds__(256, 2)
void qkv_kernel(const float* __restrict__ x,
                const float* __restrict__ bk, const float* __restrict__ bq,
                const float* __restrict__ bv)
{
    extern __shared__ char dsm[];
    char* smc = (char*)(((uintptr_t)dsm + 1023) & ~(uintptr_t)1023);
    char* Xhi = smc;          char* Xlo = smc + 8192;
    char* Whi = smc + 16384;  char* Wlo = smc + 40960;   // 24KB each (192 rows)
    const uint32_t xhi_b = smem_u32(Xhi), xlo_b = smem_u32(Xlo);
    const uint32_t whi_b = smem_u32(Whi), wlo_b = smem_u32(Wlo);

    const int tid = threadIdx.x;
    const int wid = tid >> 5, lane = tid & 31;
    const int g = lane >> 2, t = lane & 3;
    const int rw = wid & 3, cg = wid >> 2;
    const int R = 16 * rw;
    const int row0 = blockIdx.x * 64;

    float dD[12][4] = {};

#pragma unroll 1
    for (int kc = 0; kc < 16; kc++) {
        __syncthreads();   // previous MMA phase done with X/W smem
        // ---- W chunk via cp.async: 192 rows hi + 192 rows lo ----
        for (int task = tid; task < 768; task += 256) {
            int isLo = task >= 384;
            int tk = isLo ? task - 384 : task;
            int rr = tk >> 1, hf = tk & 1;
            const unsigned short* gw = isLo ? g_Wtlo : g_Wthi;
            uint32_t sb = isLo ? wlo_b : whi_b;
            const char* gp = (const char*)(gw + (size_t)rr * DD + kc * 64 + hf * 32);
#pragma unroll
            for (int i = 0; i < 4; i++)
                cp16(sb + swz((uint32_t)(rr * 128 + hf * 64 + 16 * i)), gp + 16 * i);
        }
        CP_COMMIT();
        // ---- X chunk: fp32 LDG + fast-split + STS (overlaps W cp.async) ----
        {
            int r = tid >> 2, q = tid & 3;
            const float* gp = x + (size_t)(row0 + r) * DD + kc * 64 + q * 16;
            float4 a0 = *(const float4*)(gp);
            float4 a1 = *(const float4*)(gp + 4);
            float4 a2 = *(const float4*)(gp + 8);
            float4 a3 = *(const float4*)(gp + 12);
            uint4 hi, lo;
            bf_split2(a0.x, a0.y, hi.x, lo.x);
            bf_split2(a0.z, a0.w, hi.y, lo.y);
            bf_split2(a1.x, a1.y, hi.z, lo.z);
            bf_split2(a1.z, a1.w, hi.w, lo.w);
            uint32_t off = swz((uint32_t)(r * 128 + q * 32));
            *(uint4*)(Xhi + off) = hi;
            *(uint4*)(Xlo + off) = lo;
            bf_split2(a2.x, a2.y, hi.x, lo.x);
            bf_split2(a2.z, a2.w, hi.y, lo.y);
            bf_split2(a3.x, a3.y, hi.z, lo.z);
            bf_split2(a3.z, a3.w, hi.w, lo.w);
            off = swz((uint32_t)(r * 128 + q * 32 + 16));
            *(uint4*)(Xhi + off) = hi;
            *(uint4*)(Xlo + off) = lo;
        }
        CP_WAIT(0);
        __syncthreads();

        // ---- MMA: this warp's 6 n-tile-pairs ----
#pragma unroll
        for (int kk = 0; kk < 4; kk++) {
            uint32_t ah[4], al[4];
            ldA4(ah, xhi_b, R, kk);
            ldA4(al, xlo_b, R, kk);
#pragma unroll
            for (int jl = 0; jl < 6; jl++) {
                uint32_t wh[4], wl[4];
                ldB4(wh, whi_b, cg * 12 + 2 * jl, kk);
                ldB4(wl, wlo_b, cg * 12 + 2 * jl, kk);
                uint32_t bh0[2] = { wh[0], wh[1] }, bl0[2] = { wl[0], wl[1] };
                uint32_t bh1[2] = { wh[2], wh[3] }, bl1[2] = { wl[2], wl[3] };
                mma3(dD[2 * jl],     ah, al, bh0, bl0);
                mma3(dD[2 * jl + 1], ah, al, bh1, bl1);
            }
        }
    }

    // ---- epilogue: K/Q straight to gmem (split-bf16); V staged for transpose ----
    const int r1 = R + g, r2 = r1 + 8;           // rows within 64-row tile
    float* Vst = (float*)smc;                    // 16KB fp32 stage (X area)
    __syncthreads();                             // MMA reads done
#pragma unroll
    for (int jl = 0; jl < 12; jl++) {
        int jt = cg * 12 + jl;
        int cgl = 8 * jt + 2 * t;                // global col 0..191
        int mi = cgl >> 6, cm = cgl & 63;
        if (mi < 2) {
            const float* bias = mi ? bq : bk;
            unsigned short* ohi = mi ? g_Qhi : g_Khi;
            unsigned short* olo = mi ? g_Qlo : g_Klo;
            float b0 = bias[cm], b1 = bias[cm + 1];
            uint32_t hi, lo;
            bf_split2(dD[jl][0] + b0, dD[jl][1] + b1, hi, lo);
            *(uint32_t*)(ohi + (size_t)(row0 + r1) * HH + cm) = hi;
            *(uint32_t*)(olo + (size_t)(row0 + r1) * HH + cm) = lo;
            bf_split2(dD[jl][2] + b0, dD[jl][3] + b1, hi, lo);
            *(uint32_t*)(ohi + (size_t)(row0 + r2) * HH + cm) = hi;
            *(uint32_t*)(olo + (size_t)(row0 + r2) * HH + cm) = lo;
        } else {
            float b0 = bv[cm], b1 = bv[cm + 1];
            Vst[r1 * 64 + cm] = dD[jl][0] + b0;
            Vst[r1 * 64 + cm + 1] = dD[jl][1] + b1;
            Vst[r2 * 64 + cm] = dD[jl][2] + b0;
            Vst[r2 * 64 + cm + 1] = dD[jl][3] + b1;
        }
    }
    __syncthreads();
    {   // transpose-split V: [s][h] -> g_Vt[b][h][t]
        const int b    = row0 >> 12;
        const int tloc = row0 & (TT - 1);
        const int h  = tid & 63;
        const int s0 = (tid >> 6) * 16;
        const size_t obase = (size_t)b * HH * TT + (size_t)h * TT + tloc + s0;
#pragma unroll
        for (int jj = 0; jj < 16; jj += 8) {
            uint4 hi, lo;
            bf_split2(Vst[(s0 + jj + 0) * 64 + h], Vst[(s0 + jj + 1) * 64 + h], hi.x, lo.x);
            bf_split2(Vst[(s0 + jj + 2) * 64 + h], Vst[(s0 + jj + 3) * 64 + h], hi.y, lo.y);
            bf_split2(Vst[(s0 + jj + 4) * 64 + h], Vst[(s0 + jj + 5) * 64 + h], hi.z, lo.z);
            bf_split2(Vst[(s0 + jj + 6) * 64 + h], Vst[(s0 + jj + 7) * 64 + h], hi.w, lo.w);
            *(uint4*)(g_Vthi + obase + jj) = hi;
            *(uint4*)(g_Vtlo + obase + jj) = lo;
        }
    }
}

// ---------------------------------------------------------------------------
// HMMA flash attention: R13 shape (128 t-rows, 8 warps x m16, 256 thr) with
// (a) K fragments hoisted to registers, (b) SINGLE-barrier triple-buffered
// cp.async ring: the one __syncthreads per iteration both publishes tile st
// and proves buffer (st-1)%3 drained, so prefetch(st+2) after it is safe.
// 4-way split-K -> 512 CTAs descending by work. Log2-domain softmax.
// ---------------------------------------------------------------------------
#define ATT_SMEM (131072 + 1024)
__global__ __launch_bounds__(256)
void attn_mma_kernel()
{
    extern __shared__ char dsm[];
    char* smc = (char*)(((uintptr_t)dsm + 1023) & ~(uintptr_t)1023);
    const uint32_t sa_b = smem_u32(smc);
    const uint32_t bufb = sa_b + 32768;   // 3 buffers x 32KB: Qhi,Qlo,Vhi,Vlo

    const int tid = threadIdx.x;
    const int wid = tid >> 5, lane = tid & 31;
    const int g = lane >> 2, t = lane & 3;
    const int R = 16 * wid;

    const int bid   = blockIdx.x;               // 0..511
    const int bt    = 31 - (bid >> 4);          // descending work order
    const int sub   = bid & 15;
    const int b     = sub >> 2;
    const int split = sub & 3;
    const int n     = 2 * bt + 2;
    const int st_lo = (split * n) >> 2;
    const int st_hi = (((split + 1) * n) >> 2) - 1;

    const size_t Rg = (size_t)b * TT + (size_t)bt * 128;
    const unsigned short* gQhi_b = g_Qhi + (size_t)b * TT * HH;
    const unsigned short* gQlo_b = g_Qlo + (size_t)b * TT * HH;
    const unsigned short* gVthi_b = g_Vthi + (size_t)b * HH * TT;
    const unsigned short* gVtlo_b = g_Vtlo + (size_t)b * HH * TT;
    const int trow1 = bt * 128 + R + g;
    const int trow2 = trow1 + 8;

    // ---- stage K (128 rows hi/lo) ----
    {
        int r = tid >> 1, half = tid & 1;
        const char* gph = (const char*)(g_Khi + (Rg + r) * HH + half * 32);
        const char* gpl = (const char*)(g_Klo + (Rg + r) * HH + half * 32);
#pragma unroll
        for (int i = 0; i < 4; i++) {
            uint4 vh = *(const uint4*)(gph + 16 * i);
            uint4 vl = *(const uint4*)(gpl + 16 * i);
            uint32_t off = swz((uint32_t)(r * 128 + half * 64 + 16 * i));
            *(uint4*)(smc + off) = vh;
            *(uint4*)(smc + 16384 + off) = vl;
        }
    }

    float dO[8][4] = {};
    float m1 = -CUDART_INF_F, m2 = -CUDART_INF_F, l1 = 0.f, l2 = 0.f;

    if (st_lo <= st_hi) {
        auto cp_tiles = [&](int st, uint32_t buf) {
            cp_tile64(gQhi_b + (size_t)st * 64 * HH, HH, buf, tid);
            cp_tile64(gQlo_b + (size_t)st * 64 * HH, HH, buf + 8192, tid);
            cp_tile64(gVthi_b + st * 64, TT, buf + 16384, tid);
            cp_tile64(gVtlo_b + st * 64, TT, buf + 24576, tid);
            CP_COMMIT();
        };
        // prologue: prefetch st_lo and st_lo+1
        cp_tiles(st_lo, bufb);
        if (st_lo + 1 <= st_hi) cp_tiles(st_lo + 1, bufb + 32768u);

        __syncthreads();   // K staging visible before fragment hoist
        uint32_t kfh[4][4], kfl[4][4];
#pragma unroll
        for (int kk = 0; kk < 4; kk++) {
            ldA4(kfh[kk], sa_b, R, kk);
            ldA4(kfl[kk], sa_b + 16384, R, kk);
        }

#pragma unroll 1
        for (int st = st_lo; st <= st_hi; st++) {
            const int bi = st - st_lo;
            const uint32_t cb = bufb + (uint32_t)(bi % 3) * 32768u;
            if (st + 1 <= st_hi) CP_WAIT(1); else CP_WAIT(0);
            __syncthreads();   // tile st visible; buffer (st-1)%3 drained
            if (st + 2 <= st_hi)
                cp_tiles(st + 2, bufb + (uint32_t)((bi + 2) % 3) * 32768u);

            const uint32_t qhi_b = cb, qlo_b = cb + 8192;
            const uint32_t vhi_b = cb + 16384, vlo_b = cb + 24576;

            // ---- S = K @ Q^T ----
            float dS[8][4] = {};
#pragma unroll
            for (int kk = 0; kk < 4; kk++) {
#pragma unroll
                for (int jp = 0; jp < 4; jp++) {
                    uint32_t qh[4], ql[4];
                    ldB4(qh, qhi_b, 2 * jp, kk);
                    ldB4(ql, qlo_b, 2 * jp, kk);
                    uint32_t bh0[2] = { qh[0], qh[1] }, bl0[2] = { ql[0], ql[1] };
                    uint32_t bh1[2] = { qh[2], qh[3] }, bl1[2] = { ql[2], ql[3] };
                    mma3(dS[2 * jp],     kfh[kk], kfl[kk], bh0, bl0);
                    mma3(dS[2 * jp + 1], kfh[kk], kfl[kk], bh1, bl1);
                }
            }

            // ---- scale (log2 domain) + causal mask ----
            if (st >= 2 * bt) {
#pragma unroll
                for (int j = 0; j < 8; j++) {
                    int c0 = st * 64 + 8 * j + 2 * t;
                    dS[j][0] = (c0     <= trow1) ? dS[j][0] * SCALE_L2E : -1e30f;
                    dS[j][1] = (c0 + 1 <= trow1) ? dS[j][1] * SCALE_L2E : -1e30f;
                    dS[j][2] = (c0     <= trow2) ? dS[j][2] * SCALE_L2E : -1e30f;
                    dS[j][3] = (c0 + 1 <= trow2) ? dS[j][3] * SCALE_L2E : -1e30f;
                }
            } else {
#pragma unroll
                for (int j = 0; j < 8; j++) {
                    dS[j][0] *= SCALE_L2E; dS[j][1] *= SCALE_L2E;
                    dS[j][2] *= SCALE_L2E; dS[j][3] *= SCALE_L2E;
                }
            }

            // ---- online softmax (base-2) ----
            float rmax1 = -CUDART_INF_F, rmax2 = -CUDART_INF_F;
#pragma unroll
            for (int j = 0; j < 8; j++) {
                rmax1 = fmaxf(rmax1, fmaxf(dS[j][0], dS[j][1]));
                rmax2 = fmaxf(rmax2, fmaxf(dS[j][2], dS[j][3]));
            }
            rmax1 = fmaxf(rmax1, __shfl_xor_sync(0xffffffffu, rmax1, 1));
            rmax1 = fmaxf(rmax1, __shfl_xor_sync(0xffffffffu, rmax1, 2));
            rmax2 = fmaxf(rmax2, __shfl_xor_sync(0xffffffffu, rmax2, 1));
            rmax2 = fmaxf(rmax2, __shfl_xor_sync(0xffffffffu, rmax2, 2));

            float mn1 = fmaxf(m1, rmax1), mn2 = fmaxf(m2, rmax2);
            float corr1 = ex2f(m1 - mn1), corr2 = ex2f(m2 - mn2);
            m1 = mn1; m2 = mn2;

            float sum1 = 0.f, sum2 = 0.f;
#pragma unroll
            for (int j = 0; j < 8; j++) {
                dS[j][0] = ex2f(dS[j][0] - mn1);
                dS[j][1] = ex2f(dS[j][1] - mn1);
                dS[j][2] = ex2f(dS[j][2] - mn2);
                dS[j][3] = ex2f(dS[j][3] - mn2);
                sum1 += dS[j][0] + dS[j][1];
                sum2 += dS[j][2] + dS[j][3];
            }
            sum1 += __shfl_xor_sync(0xffffffffu, sum1, 1);
            sum1 += __shfl_xor_sync(0xffffffffu, sum1, 2);
            sum2 += __shfl_xor_sync(0xffffffffu, sum2, 1);
            sum2 += __shfl_xor_sync(0xffffffffu, sum2, 2);
            l1 = l1 * corr1 + sum1;
            l2 = l2 * corr2 + sum2;
#pragma unroll
            for (int j = 0; j < 8; j++) {
                dO[j][0] *= corr1; dO[j][1] *= corr1;
                dO[j][2] *= corr2; dO[j][3] *= corr2;
            }

            // ---- O += P @ V (P fragments repacked in registers) ----
#pragma unroll
            for (int ss = 0; ss < 4; ss++) {
                uint32_t pah[4], pal[4];
                bf_split2(dS[2*ss][0],   dS[2*ss][1],   pah[0], pal[0]);
                bf_split2(dS[2*ss][2],   dS[2*ss][3],   pah[1], pal[1]);
                bf_split2(dS[2*ss+1][0], dS[2*ss+1][1], pah[2], pal[2]);
                bf_split2(dS[2*ss+1][2], dS[2*ss+1][3], pah[3], pal[3]);
#pragma unroll
                for (int jp = 0; jp < 4; jp++) {
                    uint32_t vh[4], vl[4];
                    ldB4(vh, vhi_b, 2 * jp, ss);
                    ldB4(vl, vlo_b, 2 * jp, ss);
                    uint32_t bh0[2] = { vh[0], vh[1] }, bl0[2] = { vl[0], vl[1] };
                    uint32_t bh1[2] = { vh[2], vh[3] }, bl1[2] = { vl[2], vl[3] };
                    mma3(dO[2 * jp],     pah, pal, bh0, bl0);
                    mma3(dO[2 * jp + 1], pah, pal, bh1, bl1);
                }
            }
        }
    }

    // ---- write unnormalized partial + (m, l) ----
    const size_t orow1 = (size_t)split * NROW + Rg + R + g;
    const size_t orow2 = orow1 + 8;
#pragma unroll
    for (int j = 0; j < 8; j++) {
        int c = 8 * j + 2 * t;
        *(float2*)(g_Oa + orow1 * HH + c) = make_float2(dO[j][0], dO[j][1]);
        *(float2*)(g_Oa + orow2 * HH + c) = make_float2(dO[j][2], dO[j][3]);
    }
    if (t == 0) {
        g_M[orow1] = m1; g_L[orow1] = l1;
        g_M[orow2] = m2; g_L[orow2] = l2;
    }
}

// ---------------------------------------------------------------------------
// Merge the four split partials (m stored in log2 domain -> ex2).
// ---------------------------------------------------------------------------
__global__ __launch_bounds__(256)
void combine_kernel(float* __restrict__ out)
{
    int gid = blockIdx.x * 256 + threadIdx.x;
    int r = gid >> 4, lane = gid & 15;
    float m[NSPLIT], l[NSPLIT];
#pragma unroll
    for (int i = 0; i < NSPLIT; i++) {
        m[i] = g_M[(size_t)i * NROW + r];
        l[i] = g_L[(size_t)i * NROW + r];
    }
    float M = fmaxf(fmaxf(m[0], m[1]), fmaxf(m[2], m[3]));
    float denom = 0.f, e[NSPLIT];
#pragma unroll
    for (int i = 0; i < NSPLIT; i++) {
        e[i] = ex2f(m[i] - M);
        denom += l[i] * e[i];
    }
    float inv = 1.0f / denom;
    float4 acc = make_float4(0.f, 0.f, 0.f, 0.f);
#pragma unroll
    for (int i = 0; i < NSPLIT; i++) {
        float4 a = *(const float4*)(g_Oa + ((size_t)i * NROW + r) * HH + 4 * lane);
        acc.x += a.x * e[i]; acc.y += a.y * e[i];
        acc.z += a.z * e[i]; acc.w += a.w * e[i];
    }
    acc.x *= inv; acc.y *= inv; acc.z *= inv; acc.w *= inv;
    *(float4*)(out + (size_t)r * HH + 4 * lane) = acc;
}

extern "C" void kernel_launch(void* const* d_in, const int* in_sizes, int n_in,
                              void* d_out, int out_size)
{
    const float* x  = (const float*)d_in[0];
    const float* Wk = (const float*)d_in[1];
    const float* bk = (const float*)d_in[2];
    const float* Wq = (const float*)d_in[3];
    const float* bq = (const float*)d_in[4];
    const float* Wv = (const float*)d_in[5];
    const float* bv = (const float*)d_in[6];
    float* out = (float*)d_out;

    static bool attr_done = false;
    if (!attr_done) {
        cudaFuncSetAttribute(qkv_kernel,
            cudaFuncAttributeMaxDynamicSharedMemorySize, QKV_SMEM);
        cudaFuncSetAttribute(attn_mma_kernel,
            cudaFuncAttributeMaxDynamicSharedMemorySize, ATT_SMEM);
        attr_done = true;
    }

    cvt_w_kernel<<<24, 128>>>(Wk, Wq, Wv);

    qkv_kernel<<<NROW / 64, 256, QKV_SMEM>>>(x, bk, bq, bv);

    attn_mma_kernel<<<512, 256, ATT_SMEM>>>();

    combine_kernel<<<NROW * 16 / 256, 256>>>(out);
}